// round 1
// baseline (speedup 1.0000x reference)
#include <cuda_runtime.h>
#include <math.h>

#define TT 256
#define BB 64
#define DD 1024
#define HH 2048
#define KB 8      // split-K blocks in the recurrent GEMM
#define BN 64     // output-column tile in the recurrent GEMM

// Scratch (no cudaMalloc allowed): x_proj buffer, split-K partials, arrival counters.
__device__ __align__(16) float g_xproj[(size_t)TT * BB * HH];   // 128 MB
__device__ __align__(16) float g_part[(size_t)KB * BB * HH];    // 4 MB
__device__ int g_cnt[HH / BN];                                  // 32 counters, zero-init

// ---------------------------------------------------------------------------
// x_proj = inputs[M=16384,K=1024] @ W_xh[K,N=2048] + b_h   (classic SGEMM)
// BM=BN=128, BK=8, 256 threads, 8x8 micro-tile per thread.
// ---------------------------------------------------------------------------
__global__ __launch_bounds__(256) void xproj_kernel(
    const float* __restrict__ A,
    const float* __restrict__ B,
    const float* __restrict__ bias)
{
    const int K = DD, N = HH;
    __shared__ float As[8][128];   // transposed A tile: As[k][m]
    __shared__ float Bs[8][128];

    const int tid = threadIdx.x;
    const int bn = blockIdx.x;     // N/128 = 16
    const int bm = blockIdx.y;     // M/128 = 128

    const float* Ab = A + (size_t)bm * 128 * K;
    const float* Bb = B + bn * 128;

    const int a_row = tid >> 1;          // 0..127
    const int a_col = (tid & 1) * 4;     // 0 or 4
    const int b_row = tid >> 5;          // 0..7
    const int b_col = (tid & 31) * 4;    // 0..124
    const int ty = tid >> 4;             // 0..15
    const int tx = tid & 15;             // 0..15

    float acc[8][8];
#pragma unroll
    for (int i = 0; i < 8; i++)
#pragma unroll
        for (int j = 0; j < 8; j++) acc[i][j] = 0.0f;

    for (int k0 = 0; k0 < K; k0 += 8) {
        float4 av = *(const float4*)(Ab + (size_t)a_row * K + k0 + a_col);
        As[a_col + 0][a_row] = av.x;
        As[a_col + 1][a_row] = av.y;
        As[a_col + 2][a_row] = av.z;
        As[a_col + 3][a_row] = av.w;
        float4 bv = *(const float4*)(Bb + (size_t)(k0 + b_row) * N + b_col);
        *(float4*)&Bs[b_row][b_col] = bv;
        __syncthreads();

#pragma unroll
        for (int k = 0; k < 8; k++) {
            float ar[8], br[8];
            *(float4*)&ar[0] = *(const float4*)&As[k][ty * 8];
            *(float4*)&ar[4] = *(const float4*)&As[k][ty * 8 + 4];
            *(float4*)&br[0] = *(const float4*)&Bs[k][tx * 8];
            *(float4*)&br[4] = *(const float4*)&Bs[k][tx * 8 + 4];
#pragma unroll
            for (int i = 0; i < 8; i++)
#pragma unroll
                for (int j = 0; j < 8; j++)
                    acc[i][j] += ar[i] * br[j];
        }
        __syncthreads();
    }

#pragma unroll
    for (int i = 0; i < 8; i++) {
        const size_t row = (size_t)(bm * 128 + ty * 8 + i);
#pragma unroll
        for (int j = 0; j < 8; j += 4) {
            const int col = bn * 128 + tx * 8 + j;
            float4 v;
            v.x = acc[i][j + 0] + bias[col + 0];
            v.y = acc[i][j + 1] + bias[col + 1];
            v.z = acc[i][j + 2] + bias[col + 2];
            v.w = acc[i][j + 3] + bias[col + 3];
            *(float4*)&g_xproj[row * N + col] = v;
        }
    }
}

// ---------------------------------------------------------------------------
// One recurrence step: h_out = tanh(h_prev[64,2048] @ W[2048,2048] + xproj[t])
// Split-K: grid (32 n-blocks, 8 k-blocks). Each CTA computes a [64 x 64]
// partial over a 256-wide K slice, writes it to g_part[kb], and the LAST
// arriving CTA per n-block sums the 8 partials in FIXED order (deterministic),
// adds x_proj, applies tanh, writes h_out.
// ---------------------------------------------------------------------------
__global__ __launch_bounds__(256) void step_kernel(
    const float* __restrict__ h_prev,
    const float* __restrict__ W,
    int t,
    float* __restrict__ h_out)
{
    const int N = HH, K = HH;
    const int KS = K / KB;   // 256
    const int nb = blockIdx.x;   // 0..31
    const int kb = blockIdx.y;   // 0..7

    __shared__ float hs[16][BB];   // hs[k][m]
    __shared__ float ws[16][BN];   // ws[k][n]
    __shared__ int s_last;

    const int tid = threadIdx.x;
    const int ty = tid >> 4;           // 0..15 -> rows ty*4
    const int tx = tid & 15;           // 0..15 -> cols tx*4
    const int h_r = tid >> 2;          // 0..63
    const int h_c = (tid & 3) * 4;     // 0..12
    const int w_r = tid >> 4;          // 0..15
    const int w_c = (tid & 15) * 4;    // 0..60
    const int k0base = kb * KS;

    float acc[4][4];
#pragma unroll
    for (int i = 0; i < 4; i++)
#pragma unroll
        for (int j = 0; j < 4; j++) acc[i][j] = 0.0f;

    for (int kk = 0; kk < KS; kk += 16) {
        float4 hv = *(const float4*)(h_prev + (size_t)h_r * K + k0base + kk + h_c);
        hs[h_c + 0][h_r] = hv.x;
        hs[h_c + 1][h_r] = hv.y;
        hs[h_c + 2][h_r] = hv.z;
        hs[h_c + 3][h_r] = hv.w;
        float4 wv = *(const float4*)(W + (size_t)(k0base + kk + w_r) * N + nb * BN + w_c);
        *(float4*)&ws[w_r][w_c] = wv;
        __syncthreads();

#pragma unroll
        for (int k = 0; k < 16; k++) {
            float a[4], b[4];
            *(float4*)a = *(const float4*)&hs[k][ty * 4];
            *(float4*)b = *(const float4*)&ws[k][tx * 4];
#pragma unroll
            for (int i = 0; i < 4; i++)
#pragma unroll
                for (int j = 0; j < 4; j++)
                    acc[i][j] += a[i] * b[j];
        }
        __syncthreads();
    }

    // write this CTA's partial tile
    float* P = g_part + (size_t)kb * BB * HH;
#pragma unroll
    for (int i = 0; i < 4; i++) {
        float4 v;
        v.x = acc[i][0]; v.y = acc[i][1]; v.z = acc[i][2]; v.w = acc[i][3];
        *(float4*)&P[(size_t)(ty * 4 + i) * N + nb * BN + tx * 4] = v;
    }
    __threadfence();
    __syncthreads();
    if (tid == 0) {
        int c = atomicAdd(&g_cnt[nb], 1);
        s_last = (c == KB - 1) ? 1 : 0;
        if (c == KB - 1) g_cnt[nb] = 0;   // reset for the next step's launch
    }
    __syncthreads();
    if (!s_last) return;

    // Epilogue in the last-arriving CTA for this n-block.
    const float* xp = g_xproj + (size_t)t * BB * HH;
    for (int e = tid; e < BB * (BN / 4); e += 256) {
        const int m = e / (BN / 4);
        const int c4 = (e % (BN / 4)) * 4;
        const size_t off = (size_t)m * N + nb * BN + c4;
        float4 s = __ldcg((const float4*)&g_part[off]);   // kb = 0
#pragma unroll
        for (int k2 = 1; k2 < KB; k2++) {
            float4 p = __ldcg((const float4*)&g_part[(size_t)k2 * BB * HH + off]);
            s.x += p.x; s.y += p.y; s.z += p.z; s.w += p.w;
        }
        const float4 xv = *(const float4*)&xp[off];
        float4 r;
        r.x = tanhf(s.x + xv.x);
        r.y = tanhf(s.y + xv.y);
        r.z = tanhf(s.z + xv.z);
        r.w = tanhf(s.w + xv.w);
        *(float4*)&h_out[off] = r;
    }
}

// final_state = outputs[T-1]
__global__ __launch_bounds__(256) void copy_final(const float* __restrict__ src,
                                                  float* __restrict__ dst)
{
    const int i = blockIdx.x * 256 + threadIdx.x;   // BB*HH/4 = 32768 float4s
    ((float4*)dst)[i] = ((const float4*)src)[i];
}

extern "C" void kernel_launch(void* const* d_in, const int* in_sizes, int n_in,
                              void* d_out, int out_size)
{
    (void)in_sizes; (void)n_in; (void)out_size;
    const float* inputs = (const float*)d_in[0];   // [T,B,D]
    const float* state  = (const float*)d_in[1];   // [B,H]
    const float* W_xh   = (const float*)d_in[2];   // [D,H]
    const float* W_hh   = (const float*)d_in[3];   // [H,H]
    const float* b_h    = (const float*)d_in[4];   // [H]
    float* out = (float*)d_out;   // outputs [T,B,H] then final_state [B,H]

    // 1) x_proj for all steps
    xproj_kernel<<<dim3(HH / 128, (TT * BB) / 128), 256>>>(inputs, W_xh, b_h);

    // 2) sequential scan: 256 fused split-K GEMM+tanh steps
    const float* h_prev = state;
    for (int t = 0; t < TT; t++) {
        float* h_out = out + (size_t)t * BB * HH;
        step_kernel<<<dim3(HH / BN, KB), 256>>>(h_prev, W_hh, t, h_out);
        h_prev = h_out;
    }

    // 3) final_state = outputs[T-1]
    copy_final<<<(BB * HH / 4) / 256, 256>>>(out + (size_t)(TT - 1) * BB * HH,
                                             out + (size_t)TT * BB * HH);
}